// round 2
// baseline (speedup 1.0000x reference)
#include <cuda_runtime.h>
#include <math.h>

#define T_STEPS 128
#define NE 64
#define NA 8
#define OBS 64
#define D 128
#define CH 128
#define VH 256
#define BATCH 512           // NE*NA
#define TB (T_STEPS*BATCH)  // 65536
#define ITERS 2

// ---------------- scratch (static device arrays: allocation-free) -------------
__device__ float g_emb1[TB * D];
__device__ float g_emb2[TB * D];
__device__ float g_gi[TB * 3 * D];
__device__ float g_e[TB * D];
__device__ float g_ai[TB * CH];
__device__ float g_aj[TB * CH];
__device__ float g_ctx[TB * D];
__device__ float g_d1[TB * D];
__device__ float g_v1[TB * VH];
__device__ float g_v2[TB * VH];
__device__ unsigned char g_dmask[TB];
__device__ int g_dflag;   // 0 = uint8/bool, 1 = float32, 2 = int32

// ---------------- dones dtype detection + canonicalization --------------------
// Scans only the first n BYTES (safe for every candidate dtype of an
// n-element buffer). float32 0/1 data contains bytes 0x80/0x3F -> flag 1.
// bool data has 1-bytes at arbitrary offsets -> flag 0. int32 0/1 data has
// 1-bytes only at i%4==0 -> flag 2. All-zero data: every interpretation
// yields the same (all-zero) mask, so any flag is correct.
__global__ void detect_dones_kernel(const unsigned char* __restrict__ p, int n)
{
    __shared__ int s_nonbin, s_off4;
    if (threadIdx.x == 0) { s_nonbin = 0; s_off4 = 0; }
    __syncthreads();
    int nb = 0, o4 = 0;
    for (int i = threadIdx.x; i < n; i += blockDim.x) {
        const unsigned char b = p[i];
        if (b > 1) nb = 1;
        else if (b == 1 && (i & 3)) o4 = 1;
    }
    if (nb) atomicOr(&s_nonbin, 1);
    if (o4) atomicOr(&s_off4, 1);
    __syncthreads();
    if (threadIdx.x == 0)
        g_dflag = s_nonbin ? 1 : (s_off4 ? 0 : 2);
}

__global__ void conv_dones_kernel(const void* __restrict__ p, int n)
{
    const int i = blockIdx.x * blockDim.x + threadIdx.x;
    if (i >= n) return;
    const int f = g_dflag;
    unsigned char m;
    if (f == 1)      m = (((const float*)p)[i] != 0.f);
    else if (f == 2) m = (((const int*)p)[i] != 0);
    else             m = (((const unsigned char*)p)[i] != 0);
    g_dmask[i] = m;
}

// ---------------- generic fp32 tiled GEMM -------------------------------------
// C[M,N] = epilogue( A[M,K] @ B[K,N] (+ A2 @ B2) + bias )
// flags: 1 = relu, 2 = dual (A2,B2), 4 = resid+alive: out = (Ein + relu(acc+bias)) * alive(row)
#define BM 128
#define BN 128
#define BKK 8

__global__ __launch_bounds__(256) void sgemm_kernel(
    int M, int N, int K,
    const float* __restrict__ A, const float* __restrict__ Bm,
    const float* __restrict__ A2, const float* __restrict__ B2,
    const float* __restrict__ bias, float* __restrict__ Cout,
    int flags, const float* __restrict__ Ein,
    const unsigned char* __restrict__ dones)
{
    __shared__ float As[BKK][BM];
    __shared__ float Bs[BKK][BN];

    const int tid  = threadIdx.x;
    const int brow = blockIdx.y * BM;
    const int bcol = blockIdx.x * BN;

    const int aRow = tid >> 1;          // 0..127
    const int aCol = (tid & 1) * 4;     // 0 or 4
    const int bRow = tid >> 5;          // 0..7
    const int bCol = (tid & 31) * 4;    // 0..124
    const int ty   = tid >> 4;          // 0..15
    const int tx   = tid & 15;          // 0..15

    float acc[8][8];
#pragma unroll
    for (int i = 0; i < 8; i++)
#pragma unroll
        for (int j = 0; j < 8; j++) acc[i][j] = 0.f;

    const int nsrc = (flags & 2) ? 2 : 1;
    for (int s = 0; s < nsrc; s++) {
        const float* Ap = s ? A2 : A;
        const float* Bp = s ? B2 : Bm;
        for (int k0 = 0; k0 < K; k0 += BKK) {
            float4 a4 = *(const float4*)(Ap + (size_t)(brow + aRow) * K + k0 + aCol);
            As[aCol + 0][aRow] = a4.x;
            As[aCol + 1][aRow] = a4.y;
            As[aCol + 2][aRow] = a4.z;
            As[aCol + 3][aRow] = a4.w;
            float4 b4 = *(const float4*)(Bp + (size_t)(k0 + bRow) * N + bcol + bCol);
            *(float4*)&Bs[bRow][bCol] = b4;
            __syncthreads();
#pragma unroll
            for (int k = 0; k < BKK; k++) {
                float ra[8], rb[8];
                *(float4*)(ra)     = *(const float4*)&As[k][ty * 8];
                *(float4*)(ra + 4) = *(const float4*)&As[k][ty * 8 + 4];
                *(float4*)(rb)     = *(const float4*)&Bs[k][tx * 8];
                *(float4*)(rb + 4) = *(const float4*)&Bs[k][tx * 8 + 4];
#pragma unroll
                for (int i = 0; i < 8; i++)
#pragma unroll
                    for (int j = 0; j < 8; j++)
                        acc[i][j] += ra[i] * rb[j];
            }
            __syncthreads();
        }
    }

    const bool hasb  = (bias != nullptr);
    const bool resid = (flags & 4);
    const bool dorelu = (flags & 5);
#pragma unroll
    for (int i = 0; i < 8; i++) {
        const int gr = brow + ty * 8 + i;
        float alive = 1.f;
        const float* Erow = nullptr;
        if (resid) {
            alive = dones[gr] ? 0.f : 1.f;
            Erow  = Ein + (size_t)gr * N;
        }
        float* Crow = Cout + (size_t)gr * N;
#pragma unroll
        for (int j = 0; j < 8; j++) {
            const int gc = bcol + tx * 8 + j;
            float c = acc[i][j];
            if (hasb)   c += bias[gc];
            if (dorelu) c  = fmaxf(c, 0.f);
            if (resid)  c  = (Erow[gc] + c) * alive;
            Crow[gc] = c;
        }
    }
}

// ---------------- persistent GRU scan ------------------------------------------
// 128 blocks x 4 batch rows; Wh resident in smem (transposed, stride-padded).
#define RPB 4
#define GTH 384
#define WHS_STRIDE 132
#define GRU_SMEM ((384 * WHS_STRIDE + RPB * D + RPB * 384 + D) * 4)

__global__ __launch_bounds__(GTH) void gru_kernel(
    const float* __restrict__ gi,            // (T,B,3D) = x@Wi + bi
    const unsigned char* __restrict__ dones, // (T,B) canonical mask
    const float* __restrict__ h0,            // (B,D)
    const float* __restrict__ Wh,            // (D,3D) row-major
    const float* __restrict__ bhn,           // (D)
    float* __restrict__ e_out,               // (T,B,D)  = new_h * alive
    float* __restrict__ hidden_out)          // (B,D)
{
    extern __shared__ float sm[];
    float* Whs  = sm;                          // [384][WHS_STRIDE]  (Whs[n][k] = Wh[k][n])
    float* hs   = Whs + 384 * WHS_STRIDE;      // [RPB][D]
    float* ghs  = hs + RPB * D;                // [RPB][384]
    float* sbhn = ghs + RPB * 384;             // [D]

    const int tid = threadIdx.x;               // 0..383 (column id)
    const int rowbase = blockIdx.x * RPB;

    // load Wh transposed into smem
    for (int k = 0; k < D; k++)
        Whs[tid * WHS_STRIDE + k] = Wh[(size_t)k * (3 * D) + tid];
    if (tid < D) sbhn[tid] = bhn[tid];
    for (int idx = tid; idx < RPB * D; idx += GTH)
        hs[idx] = h0[(size_t)(rowbase + (idx >> 7)) * D + (idx & 127)];
    __syncthreads();

    for (int t = 0; t < T_STEPS; t++) {
        // reset h where done
        for (int idx = tid; idx < RPB * D; idx += GTH) {
            const int r = idx >> 7;
            if (dones[t * BATCH + rowbase + r]) hs[idx] = 0.f;
        }
        __syncthreads();

        // gh[r][tid] = sum_k hs[r][k] * Wh[k][tid]
        {
            float a0 = 0.f, a1 = 0.f, a2 = 0.f, a3 = 0.f;
            const float* wp = Whs + tid * WHS_STRIDE;
#pragma unroll 8
            for (int k = 0; k < D; k += 4) {
                const float4 w4 = *(const float4*)(wp + k);
                float4 hv;
                hv = *(const float4*)(hs + 0 * D + k);
                a0 += w4.x * hv.x + w4.y * hv.y + w4.z * hv.z + w4.w * hv.w;
                hv = *(const float4*)(hs + 1 * D + k);
                a1 += w4.x * hv.x + w4.y * hv.y + w4.z * hv.z + w4.w * hv.w;
                hv = *(const float4*)(hs + 2 * D + k);
                a2 += w4.x * hv.x + w4.y * hv.y + w4.z * hv.z + w4.w * hv.w;
                hv = *(const float4*)(hs + 3 * D + k);
                a3 += w4.x * hv.x + w4.y * hv.y + w4.z * hv.z + w4.w * hv.w;
            }
            ghs[0 * 384 + tid] = a0;
            ghs[1 * 384 + tid] = a1;
            ghs[2 * 384 + tid] = a2;
            ghs[3 * 384 + tid] = a3;
        }
        __syncthreads();

        // gates
        for (int idx = tid; idx < RPB * D; idx += GTH) {
            const int r = idx >> 7, d = idx & 127;
            const int row = rowbase + r;
            const size_t gib = ((size_t)t * BATCH + row) * (3 * D);
            const float i_r = gi[gib + d];
            const float i_z = gi[gib + D + d];
            const float i_n = gi[gib + 2 * D + d];
            const float h_r = ghs[r * 384 + d];
            const float h_z = ghs[r * 384 + D + d];
            const float h_n = ghs[r * 384 + 2 * D + d];
            const float hprev = hs[idx];
            const float rg = 1.f / (1.f + expf(-(i_r + h_r)));
            const float zg = 1.f / (1.f + expf(-(i_z + h_z)));
            const float ng = tanhf(i_n + rg * (h_n + sbhn[d]));
            const float hn = (1.f - zg) * ng + zg * hprev;
            hs[idx] = hn;
            const float alive = dones[t * BATCH + row] ? 0.f : 1.f;
            e_out[((size_t)t * BATCH + row) * D + d] = hn * alive;
        }
        // next loop iteration's reset touches the same idx->thread mapping,
        // and the __syncthreads() after reset orders everything before gh reads.
    }
    __syncthreads();
    for (int idx = tid; idx < RPB * D; idx += GTH)
        hidden_out[(size_t)(rowbase + (idx >> 7)) * D + (idx & 127)] = hs[idx];
}

// ---------------- fused pairwise-coupling C + context ---------------------------
// one block per (t, group): computes 8x8 coupling matrix then context = C @ e_group
__global__ __launch_bounds__(256) void couple_ctx_kernel(
    const float* __restrict__ e, const float* __restrict__ ai,
    const float* __restrict__ aj, const float* __restrict__ chb,
    const float* __restrict__ cow, const float* __restrict__ cob,
    const unsigned char* __restrict__ dones, float* __restrict__ ctx)
{
    __shared__ float sai[NA * CH], saj[NA * CH], se[NA * D];
    __shared__ float sb[CH], sw[CH];
    __shared__ float sC[NA * NA];
    __shared__ float salive[NA];

    const int g  = blockIdx.x;        // t*NE + group
    const int t  = g >> 6;
    const int eg = g & 63;
    const size_t base = (size_t)g * NA * D;   // row t*B + eg*8 == g*8
    const int tid = threadIdx.x;

    {
        const int idx = tid * 4;      // 256 threads x float4 == 1024 floats
        *(float4*)&sai[idx] = *(const float4*)&ai[base + idx];
        *(float4*)&saj[idx] = *(const float4*)&aj[base + idx];
        *(float4*)&se[idx]  = *(const float4*)&e[base + idx];
    }
    if (tid < CH) { sb[tid] = chb[tid]; sw[tid] = cow[tid]; }
    if (tid < NA) salive[tid] = dones[t * BATCH + eg * NA + tid] ? 0.f : 1.f;
    __syncthreads();

    const int warp = tid >> 5, lane = tid & 31;
    {
        const int i = warp;           // 8 warps -> 8 i-rows
        const float cb = cob[0];
        for (int j = 0; j < NA; j++) {
            float s = 0.f;
#pragma unroll
            for (int k = lane; k < CH; k += 32) {
                const float v = sai[i * CH + k] + saj[j * CH + k] + sb[k];
                s += fmaxf(v, 0.f) * sw[k];
            }
#pragma unroll
            for (int off = 16; off; off >>= 1) s += __shfl_xor_sync(0xffffffffu, s, off);
            if (lane == 0) {
                const float cv = 1.f / (1.f + expf(-(s + cb)));
                sC[i * NA + j] = (i == j) ? 0.f : cv * salive[j];
            }
        }
    }
    __syncthreads();

    for (int idx = tid; idx < NA * D; idx += 256) {
        const int i = idx >> 7, d = idx & 127;
        float s = 0.f;
#pragma unroll
        for (int j = 0; j < NA; j++) s += sC[i * NA + j] * se[j * D + d];
        ctx[base + idx] = s;
    }
}

// ---------------- final value projection (VH -> 1) ------------------------------
__global__ __launch_bounds__(256) void vout_kernel(
    const float* __restrict__ v2, const float* __restrict__ w,
    const float* __restrict__ b, float* __restrict__ out)
{
    __shared__ float sw[VH];
    const int tid = threadIdx.x;
    sw[tid] = w[tid];                 // blockDim == VH == 256
    __syncthreads();
    const int warp = tid >> 5, lane = tid & 31;
    const int row = blockIdx.x * 8 + warp;
    const float* vp = v2 + (size_t)row * VH;
    float s = 0.f;
#pragma unroll
    for (int k = lane; k < VH; k += 32) s += vp[k] * sw[k];
#pragma unroll
    for (int off = 16; off; off >>= 1) s += __shfl_xor_sync(0xffffffffu, s, off);
    if (lane == 0) out[row] = s + b[0];
}

// ---------------- launcher -------------------------------------------------------
extern "C" void kernel_launch(void* const* d_in, const int* in_sizes, int n_in,
                              void* d_out, int out_size)
{
    const float* hidden = (const float*)d_in[0];
    const float* obs    = (const float*)d_in[1];
    const void*  dones_raw = d_in[2];
    const float* e1w = (const float*)d_in[3];
    const float* e1b = (const float*)d_in[4];
    const float* e2w = (const float*)d_in[5];
    const float* e2b = (const float*)d_in[6];
    const float* gWi = (const float*)d_in[7];
    const float* gbi = (const float*)d_in[8];
    const float* gWh = (const float*)d_in[9];
    const float* gbhn = (const float*)d_in[10];
    const float* chw = (const float*)d_in[11];
    const float* chb = (const float*)d_in[12];
    const float* cow = (const float*)d_in[13];
    const float* cob = (const float*)d_in[14];
    const float* uhw = (const float*)d_in[15];
    const float* uhb = (const float*)d_in[16];
    const float* uow = (const float*)d_in[17];
    const float* uob = (const float*)d_in[18];
    const float* v1w = (const float*)d_in[19];
    const float* v1b = (const float*)d_in[20];
    const float* v2w = (const float*)d_in[21];
    const float* v2b = (const float*)d_in[22];
    const float* vow = (const float*)d_in[23];
    const float* vob = (const float*)d_in[24];

    float* out_hidden = (float*)d_out;                 // (B, D)
    float* out_values = (float*)d_out + BATCH * D;     // (T, B)

    float *emb1, *emb2, *gi, *e, *ai, *aj, *ctx, *d1, *v1, *v2;
    unsigned char* dmask;
    cudaGetSymbolAddress((void**)&emb1, g_emb1);
    cudaGetSymbolAddress((void**)&emb2, g_emb2);
    cudaGetSymbolAddress((void**)&gi,   g_gi);
    cudaGetSymbolAddress((void**)&e,    g_e);
    cudaGetSymbolAddress((void**)&ai,   g_ai);
    cudaGetSymbolAddress((void**)&aj,   g_aj);
    cudaGetSymbolAddress((void**)&ctx,  g_ctx);
    cudaGetSymbolAddress((void**)&d1,   g_d1);
    cudaGetSymbolAddress((void**)&v1,   g_v1);
    cudaGetSymbolAddress((void**)&v2,   g_v2);
    cudaGetSymbolAddress((void**)&dmask, g_dmask);

    cudaFuncSetAttribute(gru_kernel, cudaFuncAttributeMaxDynamicSharedMemorySize, GRU_SMEM);

    const int M = TB;
    const dim3 blk(256);

    // canonicalize dones (dtype-agnostic)
    detect_dones_kernel<<<1, 256>>>((const unsigned char*)dones_raw, TB);
    conv_dones_kernel<<<TB / 256, 256>>>(dones_raw, TB);

    // embed1: relu(obs @ e1w + e1b)
    sgemm_kernel<<<dim3(D / BN, M / BM), blk>>>(M, D, OBS, obs, e1w,
        nullptr, nullptr, e1b, emb1, 1, nullptr, nullptr);
    // embed2: relu(emb1 @ e2w + e2b)
    sgemm_kernel<<<dim3(D / BN, M / BM), blk>>>(M, D, D, emb1, e2w,
        nullptr, nullptr, e2b, emb2, 1, nullptr, nullptr);
    // gi = emb2 @ gWi + gbi  (all timesteps at once)
    sgemm_kernel<<<dim3(3 * D / BN, M / BM), blk>>>(M, 3 * D, D, emb2, gWi,
        nullptr, nullptr, gbi, gi, 0, nullptr, nullptr);
    // sequential GRU scan (batch-parallel across blocks)
    gru_kernel<<<BATCH / RPB, GTH, GRU_SMEM>>>(gi, dmask, hidden, gWh, gbhn, e, out_hidden);

    for (int it = 0; it < ITERS; it++) {
        // a_i = e @ W1 ; a_j = e @ W2   (W1/W2 = halves of couple_h_w)
        sgemm_kernel<<<dim3(CH / BN, M / BM), blk>>>(M, CH, D, e, chw,
            nullptr, nullptr, nullptr, ai, 0, nullptr, nullptr);
        sgemm_kernel<<<dim3(CH / BN, M / BM), blk>>>(M, CH, D, e, chw + (size_t)D * CH,
            nullptr, nullptr, nullptr, aj, 0, nullptr, nullptr);
        // fused C + context
        couple_ctx_kernel<<<T_STEPS * NE, 256>>>(e, ai, aj, chb, cow, cob, dmask, ctx);
        // d1 = relu(e @ U1 + ctx @ U2 + uhb)
        sgemm_kernel<<<dim3(D / BN, M / BM), blk>>>(M, D, D, e, uhw,
            ctx, uhw + (size_t)D * D, uhb, d1, 1 | 2, nullptr, nullptr);
        // e = (e + relu(d1 @ uow + uob)) * alive   (in place)
        sgemm_kernel<<<dim3(D / BN, M / BM), blk>>>(M, D, D, d1, uow,
            nullptr, nullptr, uob, e, 4, e, dmask);
    }

    // value head
    sgemm_kernel<<<dim3(VH / BN, M / BM), blk>>>(M, VH, D, e, v1w,
        nullptr, nullptr, v1b, v1, 1, nullptr, nullptr);
    sgemm_kernel<<<dim3(VH / BN, M / BM), blk>>>(M, VH, VH, v1, v2w,
        nullptr, nullptr, v2b, v2, 1, nullptr, nullptr);
    vout_kernel<<<TB / 8, 256>>>(v2, vow, vob, out_values);
}

// round 3
// speedup vs baseline: 1.5229x; 1.5229x over previous
#include <cuda_runtime.h>
#include <math.h>

#define T_STEPS 128
#define NE 64
#define NA 8
#define OBS 64
#define D 128
#define CH 128
#define VH 256
#define BATCH 512           // NE*NA
#define TB (T_STEPS*BATCH)  // 65536
#define ITERS 2

// ---------------- scratch (static device arrays: allocation-free) -------------
__device__ float g_emb1[TB * D];
__device__ float g_emb2[TB * D];
__device__ float g_gi[TB * 3 * D];
__device__ float g_e[TB * D];
__device__ float g_ai[TB * CH];
__device__ float g_aj[TB * CH];
__device__ float g_ctx[TB * D];
__device__ float g_d1[TB * D];
__device__ float g_v1[TB * VH];
__device__ float g_v2[TB * VH];
__device__ unsigned char g_dmask[TB];
__device__ int g_dflag;   // 0 = uint8/bool, 1 = float32, 2 = int32

// ---------------- dones dtype detection + canonicalization --------------------
__global__ void detect_dones_kernel(const unsigned char* __restrict__ p, int n)
{
    __shared__ int s_nonbin, s_off4;
    if (threadIdx.x == 0) { s_nonbin = 0; s_off4 = 0; }
    __syncthreads();
    int nb = 0, o4 = 0;
    for (int i = threadIdx.x; i < n; i += blockDim.x) {
        const unsigned char b = p[i];
        if (b > 1) nb = 1;
        else if (b == 1 && (i & 3)) o4 = 1;
    }
    if (nb) atomicOr(&s_nonbin, 1);
    if (o4) atomicOr(&s_off4, 1);
    __syncthreads();
    if (threadIdx.x == 0)
        g_dflag = s_nonbin ? 1 : (s_off4 ? 0 : 2);
}

__global__ void conv_dones_kernel(const void* __restrict__ p, int n)
{
    const int i = blockIdx.x * blockDim.x + threadIdx.x;
    if (i >= n) return;
    const int f = g_dflag;
    unsigned char m;
    if (f == 1)      m = (((const float*)p)[i] != 0.f);
    else if (f == 2) m = (((const int*)p)[i] != 0);
    else             m = (((const unsigned char*)p)[i] != 0);
    g_dmask[i] = m;
}

// ---------------- TF32 tensor-core GEMM (3xTF32 precision) --------------------
// C[M,N] = epilogue( A[M,K] @ B[K,N] (+ A2 @ B2) + bias )
// flags: 1 = relu, 2 = dual, 4 = resid+alive: out = (Ein + relu(acc+bias)) * alive(row)
#define BM 128
#define BN 128
#define BK 16
#define AST 20      // As row stride (floats)  -> conflict-free frag reads
#define BST 136     // Bs row stride (floats)  -> conflict-free frag reads

__device__ __forceinline__ float tf32_rna(float x)
{
    unsigned int u;
    asm("cvt.rna.tf32.f32 %0, %1;" : "=r"(u) : "f"(x));
    return __uint_as_float(u);
}

__device__ __forceinline__ void mma_tf32(float* c, const unsigned int* a, const unsigned int* b)
{
    asm volatile(
        "mma.sync.aligned.m16n8k8.row.col.f32.tf32.tf32.f32 "
        "{%0,%1,%2,%3}, {%4,%5,%6,%7}, {%8,%9}, {%0,%1,%2,%3};"
        : "+f"(c[0]), "+f"(c[1]), "+f"(c[2]), "+f"(c[3])
        : "r"(a[0]), "r"(a[1]), "r"(a[2]), "r"(a[3]), "r"(b[0]), "r"(b[1]));
}

__global__ __launch_bounds__(256) void tgemm_kernel(
    int M, int N, int K,
    const float* __restrict__ A, const float* __restrict__ Bm,
    const float* __restrict__ A2, const float* __restrict__ B2,
    const float* __restrict__ bias, float* __restrict__ Cout,
    int flags, const float* __restrict__ Ein,
    const unsigned char* __restrict__ dones)
{
    __shared__ float As[2][BM * AST];   // [hi/lo][m][k]
    __shared__ float Bs[2][BK * BST];   // [hi/lo][k][n]

    const int tid  = threadIdx.x;
    const int brow = blockIdx.y * BM;
    const int bcol = blockIdx.x * BN;
    const int w    = tid >> 5, lane = tid & 31;
    const int gid  = lane >> 2, tig = lane & 3;
    const int wm   = (w & 1) * 64;       // warp m-offset in block tile
    const int wn   = (w >> 1) * 32;      // warp n-offset

    const int arow0 = tid >> 2;          // 0..63  (+64 on pass 1)
    const int afc   = (tid & 3) * 4;     // k-col within tile
    const int brw0  = tid >> 5;          // 0..7   (+8 on pass 1)
    const int bfc   = (tid & 31) * 4;    // n-col within tile

    float acc[4][4][4];
#pragma unroll
    for (int i = 0; i < 4; i++)
#pragma unroll
        for (int j = 0; j < 4; j++)
#pragma unroll
            for (int q = 0; q < 4; q++) acc[i][j][q] = 0.f;

    const int nsrc = (flags & 2) ? 2 : 1;
    const int tilesPerSrc = K / BK;
    const int ntiles = nsrc * tilesPerSrc;

    float4 rA[2], rB[2];

    // register prefetch of tile t
    auto loadTile = [&](int t) {
        const int s  = (t >= tilesPerSrc) ? 1 : 0;
        const int k0 = (t - s * tilesPerSrc) * BK;
        const float* Ap = s ? A2 : A;
        const float* Bp = s ? B2 : Bm;
        rA[0] = *(const float4*)(Ap + (size_t)(brow + arow0) * K + k0 + afc);
        rA[1] = *(const float4*)(Ap + (size_t)(brow + arow0 + 64) * K + k0 + afc);
        rB[0] = *(const float4*)(Bp + (size_t)(k0 + brw0) * N + bcol + bfc);
        rB[1] = *(const float4*)(Bp + (size_t)(k0 + brw0 + 8) * N + bcol + bfc);
    };

    loadTile(0);

    for (int t = 0; t < ntiles; t++) {
        __syncthreads();   // previous compute done before smem overwrite
        // split hi/lo and stage to smem
#pragma unroll
        for (int p = 0; p < 2; p++) {
            float4 v = rA[p], h, l;
            h.x = tf32_rna(v.x); l.x = v.x - h.x;
            h.y = tf32_rna(v.y); l.y = v.y - h.y;
            h.z = tf32_rna(v.z); l.z = v.z - h.z;
            h.w = tf32_rna(v.w); l.w = v.w - h.w;
            const int row = arow0 + p * 64;
            *(float4*)&As[0][row * AST + afc] = h;
            *(float4*)&As[1][row * AST + afc] = l;

            v = rB[p];
            h.x = tf32_rna(v.x); l.x = v.x - h.x;
            h.y = tf32_rna(v.y); l.y = v.y - h.y;
            h.z = tf32_rna(v.z); l.z = v.z - h.z;
            h.w = tf32_rna(v.w); l.w = v.w - h.w;
            const int r = brw0 + p * 8;
            *(float4*)&Bs[0][r * BST + bfc] = h;
            *(float4*)&Bs[1][r * BST + bfc] = l;
        }
        __syncthreads();

        if (t + 1 < ntiles) loadTile(t + 1);  // prefetch hides under mma

        // compute: 2 k-chunks of 8
#pragma unroll
        for (int kc = 0; kc < BK; kc += 8) {
            unsigned int bh[4][2], bl[4][2];
#pragma unroll
            for (int ns = 0; ns < 4; ns++) {
                const int n = wn + ns * 8 + gid;
                bh[ns][0] = __float_as_uint(Bs[0][(kc + tig) * BST + n]);
                bh[ns][1] = __float_as_uint(Bs[0][(kc + tig + 4) * BST + n]);
                bl[ns][0] = __float_as_uint(Bs[1][(kc + tig) * BST + n]);
                bl[ns][1] = __float_as_uint(Bs[1][(kc + tig + 4) * BST + n]);
            }
#pragma unroll
            for (int ms = 0; ms < 4; ms++) {
                const int m0 = wm + ms * 16 + gid;
                unsigned int ah[4], al[4];
                ah[0] = __float_as_uint(As[0][m0 * AST + kc + tig]);
                ah[1] = __float_as_uint(As[0][(m0 + 8) * AST + kc + tig]);
                ah[2] = __float_as_uint(As[0][m0 * AST + kc + tig + 4]);
                ah[3] = __float_as_uint(As[0][(m0 + 8) * AST + kc + tig + 4]);
                al[0] = __float_as_uint(As[1][m0 * AST + kc + tig]);
                al[1] = __float_as_uint(As[1][(m0 + 8) * AST + kc + tig]);
                al[2] = __float_as_uint(As[1][m0 * AST + kc + tig + 4]);
                al[3] = __float_as_uint(As[1][(m0 + 8) * AST + kc + tig + 4]);
#pragma unroll
                for (int ns = 0; ns < 4; ns++) {
                    mma_tf32(acc[ms][ns], ah, bh[ns]);   // hi*hi
                    mma_tf32(acc[ms][ns], ah, bl[ns]);   // hi*lo
                    mma_tf32(acc[ms][ns], al, bh[ns]);   // lo*hi
                }
            }
        }
    }

    // epilogue
    const bool hasb   = (bias != nullptr);
    const bool resid  = (flags & 4);
    const bool dorelu = (flags & 5);
#pragma unroll
    for (int ms = 0; ms < 4; ms++) {
        const int r0 = brow + wm + ms * 16 + gid;
        const int r1 = r0 + 8;
        float alive0 = 1.f, alive1 = 1.f;
        const float *E0 = nullptr, *E1 = nullptr;
        if (resid) {
            alive0 = dones[r0] ? 0.f : 1.f;
            alive1 = dones[r1] ? 0.f : 1.f;
            E0 = Ein + (size_t)r0 * N;
            E1 = Ein + (size_t)r1 * N;
        }
#pragma unroll
        for (int ns = 0; ns < 4; ns++) {
            const int c = bcol + wn + ns * 8 + tig * 2;
            float b0 = 0.f, b1 = 0.f;
            if (hasb) { b0 = bias[c]; b1 = bias[c + 1]; }
            float v0 = acc[ms][ns][0] + b0;
            float v1 = acc[ms][ns][1] + b1;
            float v2 = acc[ms][ns][2] + b0;
            float v3 = acc[ms][ns][3] + b1;
            if (dorelu) {
                v0 = fmaxf(v0, 0.f); v1 = fmaxf(v1, 0.f);
                v2 = fmaxf(v2, 0.f); v3 = fmaxf(v3, 0.f);
            }
            if (resid) {
                v0 = (E0[c] + v0) * alive0;     v1 = (E0[c + 1] + v1) * alive0;
                v2 = (E1[c] + v2) * alive1;     v3 = (E1[c + 1] + v3) * alive1;
            }
            float2 o0 = make_float2(v0, v1);
            float2 o1 = make_float2(v2, v3);
            *(float2*)&Cout[(size_t)r0 * N + c] = o0;
            *(float2*)&Cout[(size_t)r1 * N + c] = o1;
        }
    }
}

// ---------------- persistent GRU scan ------------------------------------------
#define RPB 4
#define GTH 384
#define WHS_STRIDE 132
#define GRU_SMEM ((384 * WHS_STRIDE + RPB * D + RPB * 384 + D) * 4)

__global__ __launch_bounds__(GTH) void gru_kernel(
    const float* __restrict__ gi,            // (T,B,3D) = x@Wi + bi
    const unsigned char* __restrict__ dones, // (T,B) canonical mask
    const float* __restrict__ h0,            // (B,D)
    const float* __restrict__ Wh,            // (D,3D) row-major
    const float* __restrict__ bhn,           // (D)
    float* __restrict__ e_out,               // (T,B,D)  = new_h * alive
    float* __restrict__ hidden_out)          // (B,D)
{
    extern __shared__ float sm[];
    float* Whs  = sm;                          // [384][WHS_STRIDE]
    float* hs   = Whs + 384 * WHS_STRIDE;      // [RPB][D]
    float* ghs  = hs + RPB * D;                // [RPB][384]
    float* sbhn = ghs + RPB * 384;             // [D]

    const int tid = threadIdx.x;
    const int rowbase = blockIdx.x * RPB;

    for (int k = 0; k < D; k++)
        Whs[tid * WHS_STRIDE + k] = Wh[(size_t)k * (3 * D) + tid];
    if (tid < D) sbhn[tid] = bhn[tid];
    for (int idx = tid; idx < RPB * D; idx += GTH)
        hs[idx] = h0[(size_t)(rowbase + (idx >> 7)) * D + (idx & 127)];
    __syncthreads();

    for (int t = 0; t < T_STEPS; t++) {
        for (int idx = tid; idx < RPB * D; idx += GTH) {
            const int r = idx >> 7;
            if (dones[t * BATCH + rowbase + r]) hs[idx] = 0.f;
        }
        __syncthreads();

        {
            float a0 = 0.f, a1 = 0.f, a2 = 0.f, a3 = 0.f;
            const float* wp = Whs + tid * WHS_STRIDE;
#pragma unroll 8
            for (int k = 0; k < D; k += 4) {
                const float4 w4 = *(const float4*)(wp + k);
                float4 hv;
                hv = *(const float4*)(hs + 0 * D + k);
                a0 += w4.x * hv.x + w4.y * hv.y + w4.z * hv.z + w4.w * hv.w;
                hv = *(const float4*)(hs + 1 * D + k);
                a1 += w4.x * hv.x + w4.y * hv.y + w4.z * hv.z + w4.w * hv.w;
                hv = *(const float4*)(hs + 2 * D + k);
                a2 += w4.x * hv.x + w4.y * hv.y + w4.z * hv.z + w4.w * hv.w;
                hv = *(const float4*)(hs + 3 * D + k);
                a3 += w4.x * hv.x + w4.y * hv.y + w4.z * hv.z + w4.w * hv.w;
            }
            ghs[0 * 384 + tid] = a0;
            ghs[1 * 384 + tid] = a1;
            ghs[2 * 384 + tid] = a2;
            ghs[3 * 384 + tid] = a3;
        }
        __syncthreads();

        for (int idx = tid; idx < RPB * D; idx += GTH) {
            const int r = idx >> 7, d = idx & 127;
            const int row = rowbase + r;
            const size_t gib = ((size_t)t * BATCH + row) * (3 * D);
            const float i_r = gi[gib + d];
            const float i_z = gi[gib + D + d];
            const float i_n = gi[gib + 2 * D + d];
            const float h_r = ghs[r * 384 + d];
            const float h_z = ghs[r * 384 + D + d];
            const float h_n = ghs[r * 384 + 2 * D + d];
            const float hprev = hs[idx];
            const float rg = 1.f / (1.f + expf(-(i_r + h_r)));
            const float zg = 1.f / (1.f + expf(-(i_z + h_z)));
            const float ng = tanhf(i_n + rg * (h_n + sbhn[d]));
            const float hn = (1.f - zg) * ng + zg * hprev;
            hs[idx] = hn;
            const float alive = dones[t * BATCH + row] ? 0.f : 1.f;
            e_out[((size_t)t * BATCH + row) * D + d] = hn * alive;
        }
    }
    __syncthreads();
    for (int idx = tid; idx < RPB * D; idx += GTH)
        hidden_out[(size_t)(rowbase + (idx >> 7)) * D + (idx & 127)] = hs[idx];
}

// ---------------- fused pairwise-coupling C + context ---------------------------
__global__ __launch_bounds__(256) void couple_ctx_kernel(
    const float* __restrict__ e, const float* __restrict__ ai,
    const float* __restrict__ aj, const float* __restrict__ chb,
    const float* __restrict__ cow, const float* __restrict__ cob,
    const unsigned char* __restrict__ dones, float* __restrict__ ctx)
{
    __shared__ float sai[NA * CH], saj[NA * CH], se[NA * D];
    __shared__ float sb[CH], sw[CH];
    __shared__ float sC[NA * NA];
    __shared__ float salive[NA];

    const int g  = blockIdx.x;        // t*NE + group
    const int t  = g >> 6;
    const int eg = g & 63;
    const size_t base = (size_t)g * NA * D;
    const int tid = threadIdx.x;

    {
        const int idx = tid * 4;
        *(float4*)&sai[idx] = *(const float4*)&ai[base + idx];
        *(float4*)&saj[idx] = *(const float4*)&aj[base + idx];
        *(float4*)&se[idx]  = *(const float4*)&e[base + idx];
    }
    if (tid < CH) { sb[tid] = chb[tid]; sw[tid] = cow[tid]; }
    if (tid < NA) salive[tid] = dones[t * BATCH + eg * NA + tid] ? 0.f : 1.f;
    __syncthreads();

    const int warp = tid >> 5, lane = tid & 31;
    {
        const int i = warp;
        const float cb = cob[0];
        for (int j = 0; j < NA; j++) {
            float s = 0.f;
#pragma unroll
            for (int k = lane; k < CH; k += 32) {
                const float v = sai[i * CH + k] + saj[j * CH + k] + sb[k];
                s += fmaxf(v, 0.f) * sw[k];
            }
#pragma unroll
            for (int off = 16; off; off >>= 1) s += __shfl_xor_sync(0xffffffffu, s, off);
            if (lane == 0) {
                const float cv = 1.f / (1.f + expf(-(s + cb)));
                sC[i * NA + j] = (i == j) ? 0.f : cv * salive[j];
            }
        }
    }
    __syncthreads();

    for (int idx = tid; idx < NA * D; idx += 256) {
        const int i = idx >> 7, d = idx & 127;
        float s = 0.f;
#pragma unroll
        for (int j = 0; j < NA; j++) s += sC[i * NA + j] * se[j * D + d];
        ctx[base + idx] = s;
    }
}

// ---------------- final value projection (VH -> 1) ------------------------------
__global__ __launch_bounds__(256) void vout_kernel(
    const float* __restrict__ v2, const float* __restrict__ w,
    const float* __restrict__ b, float* __restrict__ out)
{
    __shared__ float sw[VH];
    const int tid = threadIdx.x;
    sw[tid] = w[tid];
    __syncthreads();
    const int warp = tid >> 5, lane = tid & 31;
    const int row = blockIdx.x * 8 + warp;
    const float* vp = v2 + (size_t)row * VH;
    float s = 0.f;
#pragma unroll
    for (int k = lane; k < VH; k += 32) s += vp[k] * sw[k];
#pragma unroll
    for (int off = 16; off; off >>= 1) s += __shfl_xor_sync(0xffffffffu, s, off);
    if (lane == 0) out[row] = s + b[0];
}

// ---------------- launcher -------------------------------------------------------
extern "C" void kernel_launch(void* const* d_in, const int* in_sizes, int n_in,
                              void* d_out, int out_size)
{
    const float* hidden = (const float*)d_in[0];
    const float* obs    = (const float*)d_in[1];
    const void*  dones_raw = d_in[2];
    const float* e1w = (const float*)d_in[3];
    const float* e1b = (const float*)d_in[4];
    const float* e2w = (const float*)d_in[5];
    const float* e2b = (const float*)d_in[6];
    const float* gWi = (const float*)d_in[7];
    const float* gbi = (const float*)d_in[8];
    const float* gWh = (const float*)d_in[9];
    const float* gbhn = (const float*)d_in[10];
    const float* chw = (const float*)d_in[11];
    const float* chb = (const float*)d_in[12];
    const float* cow = (const float*)d_in[13];
    const float* cob = (const float*)d_in[14];
    const float* uhw = (const float*)d_in[15];
    const float* uhb = (const float*)d_in[16];
    const float* uow = (const float*)d_in[17];
    const float* uob = (const float*)d_in[18];
    const float* v1w = (const float*)d_in[19];
    const float* v1b = (const float*)d_in[20];
    const float* v2w = (const float*)d_in[21];
    const float* v2b = (const float*)d_in[22];
    const float* vow = (const float*)d_in[23];
    const float* vob = (const float*)d_in[24];

    float* out_hidden = (float*)d_out;                 // (B, D)
    float* out_values = (float*)d_out + BATCH * D;     // (T, B)

    float *emb1, *emb2, *gi, *e, *ai, *aj, *ctx, *d1, *v1, *v2;
    unsigned char* dmask;
    cudaGetSymbolAddress((void**)&emb1, g_emb1);
    cudaGetSymbolAddress((void**)&emb2, g_emb2);
    cudaGetSymbolAddress((void**)&gi,   g_gi);
    cudaGetSymbolAddress((void**)&e,    g_e);
    cudaGetSymbolAddress((void**)&ai,   g_ai);
    cudaGetSymbolAddress((void**)&aj,   g_aj);
    cudaGetSymbolAddress((void**)&ctx,  g_ctx);
    cudaGetSymbolAddress((void**)&d1,   g_d1);
    cudaGetSymbolAddress((void**)&v1,   g_v1);
    cudaGetSymbolAddress((void**)&v2,   g_v2);
    cudaGetSymbolAddress((void**)&dmask, g_dmask);

    cudaFuncSetAttribute(gru_kernel, cudaFuncAttributeMaxDynamicSharedMemorySize, GRU_SMEM);

    const int M = TB;
    const dim3 blk(256);

    // canonicalize dones (dtype-agnostic)
    detect_dones_kernel<<<1, 256>>>((const unsigned char*)dones_raw, TB);
    conv_dones_kernel<<<TB / 256, 256>>>(dones_raw, TB);

    // embed1: relu(obs @ e1w + e1b)
    tgemm_kernel<<<dim3(D / BN, M / BM), blk>>>(M, D, OBS, obs, e1w,
        nullptr, nullptr, e1b, emb1, 1, nullptr, nullptr);
    // embed2: relu(emb1 @ e2w + e2b)
    tgemm_kernel<<<dim3(D / BN, M / BM), blk>>>(M, D, D, emb1, e2w,
        nullptr, nullptr, e2b, emb2, 1, nullptr, nullptr);
    // gi = emb2 @ gWi + gbi  (all timesteps at once)
    tgemm_kernel<<<dim3(3 * D / BN, M / BM), blk>>>(M, 3 * D, D, emb2, gWi,
        nullptr, nullptr, gbi, gi, 0, nullptr, nullptr);
    // sequential GRU scan (batch-parallel across blocks)
    gru_kernel<<<BATCH / RPB, GTH, GRU_SMEM>>>(gi, dmask, hidden, gWh, gbhn, e, out_hidden);

    for (int it = 0; it < ITERS; it++) {
        tgemm_kernel<<<dim3(CH / BN, M / BM), blk>>>(M, CH, D, e, chw,
            nullptr, nullptr, nullptr, ai, 0, nullptr, nullptr);
        tgemm_kernel<<<dim3(CH / BN, M / BM), blk>>>(M, CH, D, e, chw + (size_t)D * CH,
            nullptr, nullptr, nullptr, aj, 0, nullptr, nullptr);
        couple_ctx_kernel<<<T_STEPS * NE, 256>>>(e, ai, aj, chb, cow, cob, dmask, ctx);
        // d1 = relu(e @ U1 + ctx @ U2 + uhb)
        tgemm_kernel<<<dim3(D / BN, M / BM), blk>>>(M, D, D, e, uhw,
            ctx, uhw + (size_t)D * D, uhb, d1, 1 | 2, nullptr, nullptr);
        // e = (e + relu(d1 @ uow + uob)) * alive   (in place)
        tgemm_kernel<<<dim3(D / BN, M / BM), blk>>>(M, D, D, d1, uow,
            nullptr, nullptr, uob, e, 4, e, dmask);
    }

    // value head
    tgemm_kernel<<<dim3(VH / BN, M / BM), blk>>>(M, VH, D, e, v1w,
        nullptr, nullptr, v1b, v1, 1, nullptr, nullptr);
    tgemm_kernel<<<dim3(VH / BN, M / BM), blk>>>(M, VH, VH, v1, v2w,
        nullptr, nullptr, v2b, v2, 1, nullptr, nullptr);
    vout_kernel<<<TB / 8, 256>>>(v2, vow, vob, out_values);
}

// round 4
// speedup vs baseline: 1.8600x; 1.2214x over previous
#include <cuda_runtime.h>
#include <cuda_bf16.h>
#include <math.h>

#define T_STEPS 128
#define NE 64
#define NA 8
#define OBS 64
#define D 128
#define CH 128
#define VH 256
#define BATCH 512           // NE*NA
#define TB (T_STEPS*BATCH)  // 65536
#define ITERS 2

// ---------------- scratch (static device arrays: allocation-free) -------------
__device__ float g_emb1[TB * D];
__device__ float g_emb2[TB * D];
__device__ float g_gi[TB * 3 * D];
__device__ float g_e[TB * D];
__device__ float g_aiaj[TB * 2 * CH];   // merged [ai | aj], row stride 256
__device__ float g_ctx[TB * D];
__device__ float g_d1[TB * D];
__device__ float g_v1[TB * VH];
__device__ float g_v2[TB * VH];
__device__ unsigned char g_dmask[TB];
__device__ int g_dflag;   // 0 = uint8/bool, 1 = float32, 2 = int32

// ---------------- dones dtype detection + canonicalization --------------------
__global__ void detect_dones_kernel(const unsigned char* __restrict__ p, int n)
{
    __shared__ int s_nonbin, s_off4;
    if (threadIdx.x == 0) { s_nonbin = 0; s_off4 = 0; }
    __syncthreads();
    int nb = 0, o4 = 0;
    for (int i = threadIdx.x; i < n; i += blockDim.x) {
        const unsigned char b = p[i];
        if (b > 1) nb = 1;
        else if (b == 1 && (i & 3)) o4 = 1;
    }
    if (nb) atomicOr(&s_nonbin, 1);
    if (o4) atomicOr(&s_off4, 1);
    __syncthreads();
    if (threadIdx.x == 0)
        g_dflag = s_nonbin ? 1 : (s_off4 ? 0 : 2);
}

__global__ void conv_dones_kernel(const void* __restrict__ p, int n)
{
    const int i = blockIdx.x * blockDim.x + threadIdx.x;
    if (i >= n) return;
    const int f = g_dflag;
    unsigned char m;
    if (f == 1)      m = (((const float*)p)[i] != 0.f);
    else if (f == 2) m = (((const int*)p)[i] != 0);
    else             m = (((const unsigned char*)p)[i] != 0);
    g_dmask[i] = m;
}

// ---------------- BF16 tensor-core GEMM (2-way split, 3 products ~ fp32) -------
// C[M,N] = epilogue( A[M,K] @ B[K,N] (+ A2 @ B2) + bias )
// flags: 1 relu | 2 dual-source | 4 resid+alive | 8 B column-split (Bm cols 0..127, B2 cols 128..255)
// ldb = row stride of B matrices (may differ from N).
#define BM 128
#define BN 128
#define BK 16
#define AST 12      // As row stride in u32 (8 used + pad) -> conflict-free frag reads
#define BST 136     // Bs row stride in u32 -> conflict-free frag reads

__device__ __forceinline__ unsigned pack_bf16(float lo_elem, float hi_elem)
{
    unsigned d;
    asm("cvt.rn.bf16x2.f32 %0, %1, %2;" : "=r"(d) : "f"(hi_elem), "f"(lo_elem));
    return d;
}

__device__ __forceinline__ void mma_bf16(float* c, const unsigned* a, const unsigned* b)
{
    asm volatile(
        "mma.sync.aligned.m16n8k16.row.col.f32.bf16.bf16.f32 "
        "{%0,%1,%2,%3}, {%4,%5,%6,%7}, {%8,%9}, {%0,%1,%2,%3};"
        : "+f"(c[0]), "+f"(c[1]), "+f"(c[2]), "+f"(c[3])
        : "r"(a[0]), "r"(a[1]), "r"(a[2]), "r"(a[3]), "r"(b[0]), "r"(b[1]));
}

__global__ __launch_bounds__(256) void tgemm_kernel(
    int M, int N, int K, int ldb,
    const float* __restrict__ A, const float* __restrict__ Bm,
    const float* __restrict__ A2, const float* __restrict__ B2,
    const float* __restrict__ bias, float* __restrict__ Cout,
    int flags, const float* __restrict__ Ein,
    const unsigned char* __restrict__ dones)
{
    __shared__ __align__(16) unsigned As[2][2][BM * AST];  // [buf][hi/lo][m][kpair]
    __shared__ __align__(16) unsigned Bs[2][2][(BK / 2) * BST]; // [buf][hi/lo][kpair][n]

    const int tid  = threadIdx.x;
    const int brow = blockIdx.y * BM;
    const int bcol = blockIdx.x * BN;
    const int w    = tid >> 5, lane = tid & 31;
    const int gid  = lane >> 2, tig = lane & 3;
    const int wm   = (w & 1) * 64;
    const int wn   = (w >> 1) * 32;

    const int arow0 = tid >> 2;          // 0..63 (+64 on pass 1)
    const int afc   = (tid & 3) * 4;     // k-col within tile (0,4,8,12)
    const int brw   = tid >> 5;          // k-pair row 0..7
    const int bfc   = (tid & 31) * 4;    // n-col within tile

    float acc[4][4][4];
#pragma unroll
    for (int i = 0; i < 4; i++)
#pragma unroll
        for (int j = 0; j < 4; j++)
#pragma unroll
            for (int q = 0; q < 4; q++) acc[i][j][q] = 0.f;

    const int nsrc = (flags & 2) ? 2 : 1;
    const int tilesPerSrc = K / BK;
    const int ntiles = nsrc * tilesPerSrc;

    float4 rA[2], rB[2];

    auto loadTile = [&](int t) {
        const int s  = (t >= tilesPerSrc) ? 1 : 0;
        const int k0 = (t - s * tilesPerSrc) * BK;
        const float* Ap = s ? A2 : A;
        const float* Bp;
        int bc;
        if (flags & 8) { Bp = (bcol >= BN) ? B2 : Bm; bc = 0; }
        else           { Bp = s ? B2 : Bm;            bc = bcol; }
        rA[0] = *(const float4*)(Ap + (size_t)(brow + arow0) * K + k0 + afc);
        rA[1] = *(const float4*)(Ap + (size_t)(brow + arow0 + 64) * K + k0 + afc);
        rB[0] = *(const float4*)(Bp + (size_t)(k0 + 2 * brw) * ldb + bc + bfc);
        rB[1] = *(const float4*)(Bp + (size_t)(k0 + 2 * brw + 1) * ldb + bc + bfc);
    };

    auto storeTile = [&](int buf) {
        // A: split hi/lo, pack k pairs
#pragma unroll
        for (int p = 0; p < 2; p++) {
            const float4 v = rA[p];
            const float h0 = __bfloat162float(__float2bfloat16(v.x));
            const float h1 = __bfloat162float(__float2bfloat16(v.y));
            const float h2 = __bfloat162float(__float2bfloat16(v.z));
            const float h3 = __bfloat162float(__float2bfloat16(v.w));
            const int base = (arow0 + p * 64) * AST + (tid & 3) * 2;
            *(uint2*)&As[buf][0][base] = make_uint2(pack_bf16(h0, h1), pack_bf16(h2, h3));
            *(uint2*)&As[buf][1][base] = make_uint2(pack_bf16(v.x - h0, v.y - h1),
                                                    pack_bf16(v.z - h2, v.w - h3));
        }
        // B: rows (2*brw, 2*brw+1) pack across k
        {
            const float4 va = rB[0], vb = rB[1];
            float ha0 = __bfloat162float(__float2bfloat16(va.x));
            float ha1 = __bfloat162float(__float2bfloat16(va.y));
            float ha2 = __bfloat162float(__float2bfloat16(va.z));
            float ha3 = __bfloat162float(__float2bfloat16(va.w));
            float hb0 = __bfloat162float(__float2bfloat16(vb.x));
            float hb1 = __bfloat162float(__float2bfloat16(vb.y));
            float hb2 = __bfloat162float(__float2bfloat16(vb.z));
            float hb3 = __bfloat162float(__float2bfloat16(vb.w));
            const int base = brw * BST + bfc;
            *(uint4*)&Bs[buf][0][base] = make_uint4(
                pack_bf16(ha0, hb0), pack_bf16(ha1, hb1),
                pack_bf16(ha2, hb2), pack_bf16(ha3, hb3));
            *(uint4*)&Bs[buf][1][base] = make_uint4(
                pack_bf16(va.x - ha0, vb.x - hb0), pack_bf16(va.y - ha1, vb.y - hb1),
                pack_bf16(va.z - ha2, vb.z - hb2), pack_bf16(va.w - ha3, vb.w - hb3));
        }
    };

    loadTile(0);
    storeTile(0);
    __syncthreads();

    for (int t = 0; t < ntiles; t++) {
        if (t + 1 < ntiles) loadTile(t + 1);

        const unsigned* Ash = As[t & 1][0];
        const unsigned* Asl = As[t & 1][1];
        const unsigned* Bsh = Bs[t & 1][0];
        const unsigned* Bsl = Bs[t & 1][1];

        unsigned bh[4][2], bl[4][2];
#pragma unroll
        for (int ns = 0; ns < 4; ns++) {
            const int n = wn + ns * 8 + gid;
            bh[ns][0] = Bsh[tig * BST + n];
            bh[ns][1] = Bsh[(tig + 4) * BST + n];
            bl[ns][0] = Bsl[tig * BST + n];
            bl[ns][1] = Bsl[(tig + 4) * BST + n];
        }
#pragma unroll
        for (int ms = 0; ms < 4; ms++) {
            const int m0 = wm + ms * 16 + gid;
            unsigned ah[4], al[4];
            ah[0] = Ash[m0 * AST + tig];
            ah[1] = Ash[(m0 + 8) * AST + tig];
            ah[2] = Ash[m0 * AST + tig + 4];
            ah[3] = Ash[(m0 + 8) * AST + tig + 4];
            al[0] = Asl[m0 * AST + tig];
            al[1] = Asl[(m0 + 8) * AST + tig];
            al[2] = Asl[m0 * AST + tig + 4];
            al[3] = Asl[(m0 + 8) * AST + tig + 4];
#pragma unroll
            for (int ns = 0; ns < 4; ns++) {
                mma_bf16(acc[ms][ns], ah, bh[ns]);   // hi*hi
                mma_bf16(acc[ms][ns], ah, bl[ns]);   // hi*lo
                mma_bf16(acc[ms][ns], al, bh[ns]);   // lo*hi
            }
        }

        if (t + 1 < ntiles) {
            storeTile((t + 1) & 1);   // writes other buffer; safe pre-sync
            __syncthreads();
        }
    }

    // epilogue
    const bool hasb   = (bias != nullptr);
    const bool resid  = (flags & 4);
    const bool dorelu = (flags & 5);
#pragma unroll
    for (int ms = 0; ms < 4; ms++) {
        const int r0 = brow + wm + ms * 16 + gid;
        const int r1 = r0 + 8;
        float alive0 = 1.f, alive1 = 1.f;
        const float *E0 = nullptr, *E1 = nullptr;
        if (resid) {
            alive0 = dones[r0] ? 0.f : 1.f;
            alive1 = dones[r1] ? 0.f : 1.f;
            E0 = Ein + (size_t)r0 * N;
            E1 = Ein + (size_t)r1 * N;
        }
#pragma unroll
        for (int ns = 0; ns < 4; ns++) {
            const int c = bcol + wn + ns * 8 + tig * 2;
            float b0 = 0.f, b1 = 0.f;
            if (hasb) { b0 = bias[c]; b1 = bias[c + 1]; }
            float v0 = acc[ms][ns][0] + b0;
            float v1 = acc[ms][ns][1] + b1;
            float v2 = acc[ms][ns][2] + b0;
            float v3 = acc[ms][ns][3] + b1;
            if (dorelu) {
                v0 = fmaxf(v0, 0.f); v1 = fmaxf(v1, 0.f);
                v2 = fmaxf(v2, 0.f); v3 = fmaxf(v3, 0.f);
            }
            if (resid) {
                v0 = (E0[c] + v0) * alive0;     v1 = (E0[c + 1] + v1) * alive0;
                v2 = (E1[c] + v2) * alive1;     v3 = (E1[c + 1] + v3) * alive1;
            }
            *(float2*)&Cout[(size_t)r0 * N + c] = make_float2(v0, v1);
            *(float2*)&Cout[(size_t)r1 * N + c] = make_float2(v2, v3);
        }
    }
}

// ---------------- persistent GRU scan ------------------------------------------
#define RPB 4
#define GTH 384
#define WHS_STRIDE 132
#define GRU_SMEM ((384 * WHS_STRIDE + RPB * D + RPB * 384 + D) * 4)

__global__ __launch_bounds__(GTH) void gru_kernel(
    const float* __restrict__ gi,
    const unsigned char* __restrict__ dones,
    const float* __restrict__ h0,
    const float* __restrict__ Wh,
    const float* __restrict__ bhn,
    float* __restrict__ e_out,
    float* __restrict__ hidden_out)
{
    extern __shared__ float sm[];
    float* Whs  = sm;
    float* hs   = Whs + 384 * WHS_STRIDE;
    float* ghs  = hs + RPB * D;
    float* sbhn = ghs + RPB * 384;

    const int tid = threadIdx.x;
    const int rowbase = blockIdx.x * RPB;

    for (int k = 0; k < D; k++)
        Whs[tid * WHS_STRIDE + k] = Wh[(size_t)k * (3 * D) + tid];
    if (tid < D) sbhn[tid] = bhn[tid];
    for (int idx = tid; idx < RPB * D; idx += GTH)
        hs[idx] = h0[(size_t)(rowbase + (idx >> 7)) * D + (idx & 127)];
    __syncthreads();

    for (int t = 0; t < T_STEPS; t++) {
        for (int idx = tid; idx < RPB * D; idx += GTH) {
            const int r = idx >> 7;
            if (dones[t * BATCH + rowbase + r]) hs[idx] = 0.f;
        }
        __syncthreads();

        {
            float a0 = 0.f, a1 = 0.f, a2 = 0.f, a3 = 0.f;
            const float* wp = Whs + tid * WHS_STRIDE;
#pragma unroll 8
            for (int k = 0; k < D; k += 4) {
                const float4 w4 = *(const float4*)(wp + k);
                float4 hv;
                hv = *(const float4*)(hs + 0 * D + k);
                a0 += w4.x * hv.x + w4.y * hv.y + w4.z * hv.z + w4.w * hv.w;
                hv = *(const float4*)(hs + 1 * D + k);
                a1 += w4.x * hv.x + w4.y * hv.y + w4.z * hv.z + w4.w * hv.w;
                hv = *(const float4*)(hs + 2 * D + k);
                a2 += w4.x * hv.x + w4.y * hv.y + w4.z * hv.z + w4.w * hv.w;
                hv = *(const float4*)(hs + 3 * D + k);
                a3 += w4.x * hv.x + w4.y * hv.y + w4.z * hv.z + w4.w * hv.w;
            }
            ghs[0 * 384 + tid] = a0;
            ghs[1 * 384 + tid] = a1;
            ghs[2 * 384 + tid] = a2;
            ghs[3 * 384 + tid] = a3;
        }
        __syncthreads();

        for (int idx = tid; idx < RPB * D; idx += GTH) {
            const int r = idx >> 7, d = idx & 127;
            const int row = rowbase + r;
            const size_t gib = ((size_t)t * BATCH + row) * (3 * D);
            const float i_r = gi[gib + d];
            const float i_z = gi[gib + D + d];
            const float i_n = gi[gib + 2 * D + d];
            const float h_r = ghs[r * 384 + d];
            const float h_z = ghs[r * 384 + D + d];
            const float h_n = ghs[r * 384 + 2 * D + d];
            const float hprev = hs[idx];
            const float rg = 1.f / (1.f + expf(-(i_r + h_r)));
            const float zg = 1.f / (1.f + expf(-(i_z + h_z)));
            const float ng = tanhf(i_n + rg * (h_n + sbhn[d]));
            const float hn = (1.f - zg) * ng + zg * hprev;
            hs[idx] = hn;
            const float alive = dones[t * BATCH + row] ? 0.f : 1.f;
            e_out[((size_t)t * BATCH + row) * D + d] = hn * alive;
        }
    }
    __syncthreads();
    for (int idx = tid; idx < RPB * D; idx += GTH)
        hidden_out[(size_t)(rowbase + (idx >> 7)) * D + (idx & 127)] = hs[idx];
}

// ---------------- fused pairwise-coupling C + context ---------------------------
// reads merged aiaj (row stride 256: [ai | aj])
__global__ __launch_bounds__(256) void couple_ctx_kernel(
    const float* __restrict__ e, const float* __restrict__ aiaj,
    const float* __restrict__ chb,
    const float* __restrict__ cow, const float* __restrict__ cob,
    const unsigned char* __restrict__ dones, float* __restrict__ ctx)
{
    __shared__ float sai[NA * CH], saj[NA * CH], se[NA * D];
    __shared__ float sb[CH], sw[CH];
    __shared__ float sC[NA * NA];
    __shared__ float salive[NA];

    const int g  = blockIdx.x;        // t*NE + group
    const int t  = g >> 6;
    const int eg = g & 63;
    const size_t base  = (size_t)g * NA * D;
    const size_t base2 = (size_t)g * NA * 256;
    const int tid = threadIdx.x;

#pragma unroll
    for (int q = 0; q < 2; q++) {
        const int idx = (tid + q * 256) * 4;
        const int row = idx >> 8;
        const int col = idx & 255;
        const float4 v = *(const float4*)&aiaj[base2 + idx];
        if (col < 128) *(float4*)&sai[row * 128 + col] = v;
        else           *(float4*)&saj[row * 128 + col - 128] = v;
    }
    *(float4*)&se[tid * 4] = *(const float4*)&e[base + tid * 4];
    if (tid < CH) { sb[tid] = chb[tid]; sw[tid] = cow[tid]; }
    if (tid < NA) salive[tid] = dones[t * BATCH + eg * NA + tid] ? 0.f : 1.f;
    __syncthreads();

    const int warp = tid >> 5, lane = tid & 31;
    {
        const int i = warp;
        const float cb = cob[0];
        for (int j = 0; j < NA; j++) {
            float s = 0.f;
#pragma unroll
            for (int k = lane; k < CH; k += 32) {
                const float v = sai[i * CH + k] + saj[j * CH + k] + sb[k];
                s += fmaxf(v, 0.f) * sw[k];
            }
#pragma unroll
            for (int off = 16; off; off >>= 1) s += __shfl_xor_sync(0xffffffffu, s, off);
            if (lane == 0) {
                const float cv = 1.f / (1.f + expf(-(s + cb)));
                sC[i * NA + j] = (i == j) ? 0.f : cv * salive[j];
            }
        }
    }
    __syncthreads();

    for (int idx = tid; idx < NA * D; idx += 256) {
        const int i = idx >> 7, d = idx & 127;
        float s = 0.f;
#pragma unroll
        for (int j = 0; j < NA; j++) s += sC[i * NA + j] * se[j * D + d];
        ctx[base + idx] = s;
    }
}

// ---------------- final value projection (VH -> 1) ------------------------------
__global__ __launch_bounds__(256) void vout_kernel(
    const float* __restrict__ v2, const float* __restrict__ w,
    const float* __restrict__ b, float* __restrict__ out)
{
    __shared__ float sw[VH];
    const int tid = threadIdx.x;
    sw[tid] = w[tid];
    __syncthreads();
    const int warp = tid >> 5, lane = tid & 31;
    const int row = blockIdx.x * 8 + warp;
    const float* vp = v2 + (size_t)row * VH;
    float s = 0.f;
#pragma unroll
    for (int k = lane; k < VH; k += 32) s += vp[k] * sw[k];
#pragma unroll
    for (int off = 16; off; off >>= 1) s += __shfl_xor_sync(0xffffffffu, s, off);
    if (lane == 0) out[row] = s + b[0];
}

// ---------------- launcher -------------------------------------------------------
extern "C" void kernel_launch(void* const* d_in, const int* in_sizes, int n_in,
                              void* d_out, int out_size)
{
    const float* hidden = (const float*)d_in[0];
    const float* obs    = (const float*)d_in[1];
    const void*  dones_raw = d_in[2];
    const float* e1w = (const float*)d_in[3];
    const float* e1b = (const float*)d_in[4];
    const float* e2w = (const float*)d_in[5];
    const float* e2b = (const float*)d_in[6];
    const float* gWi = (const float*)d_in[7];
    const float* gbi = (const float*)d_in[8];
    const float* gWh = (const float*)d_in[9];
    const float* gbhn = (const float*)d_in[10];
    const float* chw = (const float*)d_in[11];
    const float* chb = (const float*)d_in[12];
    const float* cow = (const float*)d_in[13];
    const float* cob = (const float*)d_in[14];
    const float* uhw = (const float*)d_in[15];
    const float* uhb = (const float*)d_in[16];
    const float* uow = (const float*)d_in[17];
    const float* uob = (const float*)d_in[18];
    const float* v1w = (const float*)d_in[19];
    const float* v1b = (const float*)d_in[20];
    const float* v2w = (const float*)d_in[21];
    const float* v2b = (const float*)d_in[22];
    const float* vow = (const float*)d_in[23];
    const float* vob = (const float*)d_in[24];

    float* out_hidden = (float*)d_out;                 // (B, D)
    float* out_values = (float*)d_out + BATCH * D;     // (T, B)

    float *emb1, *emb2, *gi, *e, *aiaj, *ctx, *d1, *v1, *v2;
    unsigned char* dmask;
    cudaGetSymbolAddress((void**)&emb1, g_emb1);
    cudaGetSymbolAddress((void**)&emb2, g_emb2);
    cudaGetSymbolAddress((void**)&gi,   g_gi);
    cudaGetSymbolAddress((void**)&e,    g_e);
    cudaGetSymbolAddress((void**)&aiaj, g_aiaj);
    cudaGetSymbolAddress((void**)&ctx,  g_ctx);
    cudaGetSymbolAddress((void**)&d1,   g_d1);
    cudaGetSymbolAddress((void**)&v1,   g_v1);
    cudaGetSymbolAddress((void**)&v2,   g_v2);
    cudaGetSymbolAddress((void**)&dmask, g_dmask);

    cudaFuncSetAttribute(gru_kernel, cudaFuncAttributeMaxDynamicSharedMemorySize, GRU_SMEM);

    const int M = TB;
    const dim3 blk(256);

    detect_dones_kernel<<<1, 256>>>((const unsigned char*)dones_raw, TB);
    conv_dones_kernel<<<TB / 256, 256>>>(dones_raw, TB);

    // embed1: relu(obs @ e1w + e1b)
    tgemm_kernel<<<dim3(D / BN, M / BM), blk>>>(M, D, OBS, D, obs, e1w,
        nullptr, nullptr, e1b, emb1, 1, nullptr, nullptr);
    // embed2: relu(emb1 @ e2w + e2b)
    tgemm_kernel<<<dim3(D / BN, M / BM), blk>>>(M, D, D, D, emb1, e2w,
        nullptr, nullptr, e2b, emb2, 1, nullptr, nullptr);
    // gi = emb2 @ gWi + gbi
    tgemm_kernel<<<dim3(3 * D / BN, M / BM), blk>>>(M, 3 * D, D, 3 * D, emb2, gWi,
        nullptr, nullptr, gbi, gi, 0, nullptr, nullptr);
    // sequential GRU scan
    gru_kernel<<<BATCH / RPB, GTH, GRU_SMEM>>>(gi, dmask, hidden, gWh, gbhn, e, out_hidden);

    for (int it = 0; it < ITERS; it++) {
        // [ai | aj] = e @ [W1 | W2]  (one N=256 GEMM, column-split B)
        tgemm_kernel<<<dim3(2 * CH / BN, M / BM), blk>>>(M, 2 * CH, D, CH, e, chw,
            nullptr, chw + (size_t)D * CH, nullptr, aiaj, 8, nullptr, nullptr);
        couple_ctx_kernel<<<T_STEPS * NE, 256>>>(e, aiaj, chb, cow, cob, dmask, ctx);
        // d1 = relu(e @ U1 + ctx @ U2 + uhb)
        tgemm_kernel<<<dim3(D / BN, M / BM), blk>>>(M, D, D, D, e, uhw,
            ctx, uhw + (size_t)D * D, uhb, d1, 1 | 2, nullptr, nullptr);
        // e = (e + relu(d1 @ uow + uob)) * alive   (in place)
        tgemm_kernel<<<dim3(D / BN, M / BM), blk>>>(M, D, D, D, d1, uow,
            nullptr, nullptr, uob, e, 4, e, dmask);
    }

    // value head
    tgemm_kernel<<<dim3(VH / BN, M / BM), blk>>>(M, VH, D, VH, e, v1w,
        nullptr, nullptr, v1b, v1, 1, nullptr, nullptr);
    tgemm_kernel<<<dim3(VH / BN, M / BM), blk>>>(M, VH, VH, VH, v1, v2w,
        nullptr, nullptr, v2b, v2, 1, nullptr, nullptr);
    vout_kernel<<<TB / 8, 256>>>(v2, vow, vob, out_values);
}

// round 5
// speedup vs baseline: 1.8619x; 1.0010x over previous
#include <cuda_runtime.h>
#include <cuda_bf16.h>
#include <math.h>

#define T_STEPS 128
#define NE 64
#define NA 8
#define OBS 64
#define D 128
#define CH 128
#define VH 256
#define BATCH 512           // NE*NA
#define TB (T_STEPS*BATCH)  // 65536
#define ITERS 2

// ---------------- scratch (static device arrays: allocation-free) -------------
__device__ float g_emb1[TB * D];
__device__ float g_emb2[TB * D];
__device__ float g_gi[TB * 3 * D];
__device__ float g_e[TB * D];
__device__ float g_aiaj[TB * 2 * CH];   // merged [ai | aj], row stride 256
__device__ float g_ctx[TB * D];
__device__ float g_d1[TB * D];
__device__ float g_v1[TB * VH];
__device__ float g_v2[TB * VH];
__device__ unsigned char g_dmask[TB];
__device__ int g_dflag;   // 0 = uint8/bool, 1 = float32, 2 = int32

// ---------------- dones dtype detection + canonicalization --------------------
__global__ void detect_dones_kernel(const unsigned char* __restrict__ p, int n)
{
    __shared__ int s_nonbin, s_off4;
    if (threadIdx.x == 0) { s_nonbin = 0; s_off4 = 0; }
    __syncthreads();
    int nb = 0, o4 = 0;
    for (int i = threadIdx.x; i < n; i += blockDim.x) {
        const unsigned char b = p[i];
        if (b > 1) nb = 1;
        else if (b == 1 && (i & 3)) o4 = 1;
    }
    if (nb) atomicOr(&s_nonbin, 1);
    if (o4) atomicOr(&s_off4, 1);
    __syncthreads();
    if (threadIdx.x == 0)
        g_dflag = s_nonbin ? 1 : (s_off4 ? 0 : 2);
}

__global__ void conv_dones_kernel(const void* __restrict__ p, int n)
{
    const int i = blockIdx.x * blockDim.x + threadIdx.x;
    if (i >= n) return;
    const int f = g_dflag;
    unsigned char m;
    if (f == 1)      m = (((const float*)p)[i] != 0.f);
    else if (f == 2) m = (((const int*)p)[i] != 0);
    else             m = (((const unsigned char*)p)[i] != 0);
    g_dmask[i] = m;
}

// ---------------- BF16 tensor-core GEMM (2-way split, 3 products ~ fp32) -------
// C[M,N] = epilogue( A[M,K] @ B[K,N] (+ A2 @ B2) + bias )
// flags: 1 relu | 2 dual-source | 4 resid+alive | 8 B column-split (Bm cols 0..127, B2 cols 128..255)
// ldb = row stride of B matrices (may differ from N).
#define BM 128
#define BN 128
#define BK 16
#define AST 12      // As row stride in u32 (8 used + pad) -> conflict-free frag reads
#define BST 136     // Bs row stride in u32 -> conflict-free frag reads

__device__ __forceinline__ unsigned pack_bf16(float lo_elem, float hi_elem)
{
    unsigned d;
    asm("cvt.rn.bf16x2.f32 %0, %1, %2;" : "=r"(d) : "f"(hi_elem), "f"(lo_elem));
    return d;
}

__device__ __forceinline__ void mma_bf16(float* c, const unsigned* a, const unsigned* b)
{
    asm volatile(
        "mma.sync.aligned.m16n8k16.row.col.f32.bf16.bf16.f32 "
        "{%0,%1,%2,%3}, {%4,%5,%6,%7}, {%8,%9}, {%0,%1,%2,%3};"
        : "+f"(c[0]), "+f"(c[1]), "+f"(c[2]), "+f"(c[3])
        : "r"(a[0]), "r"(a[1]), "r"(a[2]), "r"(a[3]), "r"(b[0]), "r"(b[1]));
}

__global__ __launch_bounds__(256) void tgemm_kernel(
    int M, int N, int K, int ldb,
    const float* __restrict__ A, const float* __restrict__ Bm,
    const float* __restrict__ A2, const float* __restrict__ B2,
    const float* __restrict__ bias, float* __restrict__ Cout,
    int flags, const float* __restrict__ Ein,
    const unsigned char* __restrict__ dones)
{
    __shared__ __align__(16) unsigned As[2][2][BM * AST];  // [buf][hi/lo][m][kpair]
    __shared__ __align__(16) unsigned Bs[2][2][(BK / 2) * BST]; // [buf][hi/lo][kpair][n]

    const int tid  = threadIdx.x;
    const int brow = blockIdx.y * BM;
    const int bcol = blockIdx.x * BN;
    const int w    = tid >> 5, lane = tid & 31;
    const int gid  = lane >> 2, tig = lane & 3;
    const int wm   = (w & 1) * 64;
    const int wn   = (w >> 1) * 32;

    const int arow0 = tid >> 2;          // 0..63 (+64 on pass 1)
    const int afc   = (tid & 3) * 4;     // k-col within tile (0,4,8,12)
    const int brw   = tid >> 5;          // k-pair row 0..7
    const int bfc   = (tid & 31) * 4;    // n-col within tile

    float acc[4][4][4];
#pragma unroll
    for (int i = 0; i < 4; i++)
#pragma unroll
        for (int j = 0; j < 4; j++)
#pragma unroll
            for (int q = 0; q < 4; q++) acc[i][j][q] = 0.f;

    const int nsrc = (flags & 2) ? 2 : 1;
    const int tilesPerSrc = K / BK;
    const int ntiles = nsrc * tilesPerSrc;

    float4 rA[2], rB[2];

    auto loadTile = [&](int t) {
        const int s  = (t >= tilesPerSrc) ? 1 : 0;
        const int k0 = (t - s * tilesPerSrc) * BK;
        const float* Ap = s ? A2 : A;
        const float* Bp;
        int bc;
        if (flags & 8) { Bp = (bcol >= BN) ? B2 : Bm; bc = 0; }
        else           { Bp = s ? B2 : Bm;            bc = bcol; }
        rA[0] = *(const float4*)(Ap + (size_t)(brow + arow0) * K + k0 + afc);
        rA[1] = *(const float4*)(Ap + (size_t)(brow + arow0 + 64) * K + k0 + afc);
        rB[0] = *(const float4*)(Bp + (size_t)(k0 + 2 * brw) * ldb + bc + bfc);
        rB[1] = *(const float4*)(Bp + (size_t)(k0 + 2 * brw + 1) * ldb + bc + bfc);
    };

    auto storeTile = [&](int buf) {
        // A: split hi/lo, pack k pairs
#pragma unroll
        for (int p = 0; p < 2; p++) {
            const float4 v = rA[p];
            const float h0 = __bfloat162float(__float2bfloat16(v.x));
            const float h1 = __bfloat162float(__float2bfloat16(v.y));
            const float h2 = __bfloat162float(__float2bfloat16(v.z));
            const float h3 = __bfloat162float(__float2bfloat16(v.w));
            const int base = (arow0 + p * 64) * AST + (tid & 3) * 2;
            *(uint2*)&As[buf][0][base] = make_uint2(pack_bf16(h0, h1), pack_bf16(h2, h3));
            *(uint2*)&As[buf][1][base] = make_uint2(pack_bf16(v.x - h0, v.y - h1),
                                                    pack_bf16(v.z - h2, v.w - h3));
        }
        // B: rows (2*brw, 2*brw+1) pack across k
        {
            const float4 va = rB[0], vb = rB[1];
            float ha0 = __bfloat162float(__float2bfloat16(va.x));
            float ha1 = __bfloat162float(__float2bfloat16(va.y));
            float ha2 = __bfloat162float(__float2bfloat16(va.z));
            float ha3 = __bfloat162float(__float2bfloat16(va.w));
            float hb0 = __bfloat162float(__float2bfloat16(vb.x));
            float hb1 = __bfloat162float(__float2bfloat16(vb.y));
            float hb2 = __bfloat162float(__float2bfloat16(vb.z));
            float hb3 = __bfloat162float(__float2bfloat16(vb.w));
            const int base = brw * BST + bfc;
            *(uint4*)&Bs[buf][0][base] = make_uint4(
                pack_bf16(ha0, hb0), pack_bf16(ha1, hb1),
                pack_bf16(ha2, hb2), pack_bf16(ha3, hb3));
            *(uint4*)&Bs[buf][1][base] = make_uint4(
                pack_bf16(va.x - ha0, vb.x - hb0), pack_bf16(va.y - ha1, vb.y - hb1),
                pack_bf16(va.z - ha2, vb.z - hb2), pack_bf16(va.w - ha3, vb.w - hb3));
        }
    };

    loadTile(0);
    storeTile(0);
    __syncthreads();

    for (int t = 0; t < ntiles; t++) {
        if (t + 1 < ntiles) loadTile(t + 1);

        const unsigned* Ash = As[t & 1][0];
        const unsigned* Asl = As[t & 1][1];
        const unsigned* Bsh = Bs[t & 1][0];
        const unsigned* Bsl = Bs[t & 1][1];

        unsigned bh[4][2], bl[4][2];
#pragma unroll
        for (int ns = 0; ns < 4; ns++) {
            const int n = wn + ns * 8 + gid;
            bh[ns][0] = Bsh[tig * BST + n];
            bh[ns][1] = Bsh[(tig + 4) * BST + n];
            bl[ns][0] = Bsl[tig * BST + n];
            bl[ns][1] = Bsl[(tig + 4) * BST + n];
        }
#pragma unroll
        for (int ms = 0; ms < 4; ms++) {
            const int m0 = wm + ms * 16 + gid;
            unsigned ah[4], al[4];
            ah[0] = Ash[m0 * AST + tig];
            ah[1] = Ash[(m0 + 8) * AST + tig];
            ah[2] = Ash[m0 * AST + tig + 4];
            ah[3] = Ash[(m0 + 8) * AST + tig + 4];
            al[0] = Asl[m0 * AST + tig];
            al[1] = Asl[(m0 + 8) * AST + tig];
            al[2] = Asl[m0 * AST + tig + 4];
            al[3] = Asl[(m0 + 8) * AST + tig + 4];
#pragma unroll
            for (int ns = 0; ns < 4; ns++) {
                mma_bf16(acc[ms][ns], ah, bh[ns]);   // hi*hi
                mma_bf16(acc[ms][ns], ah, bl[ns]);   // hi*lo
                mma_bf16(acc[ms][ns], al, bh[ns]);   // lo*hi
            }
        }

        if (t + 1 < ntiles) {
            storeTile((t + 1) & 1);   // writes other buffer; safe pre-sync
            __syncthreads();
        }
    }

    // epilogue
    const bool hasb   = (bias != nullptr);
    const bool resid  = (flags & 4);
    const bool dorelu = (flags & 5);
#pragma unroll
    for (int ms = 0; ms < 4; ms++) {
        const int r0 = brow + wm + ms * 16 + gid;
        const int r1 = r0 + 8;
        float alive0 = 1.f, alive1 = 1.f;
        const float *E0 = nullptr, *E1 = nullptr;
        if (resid) {
            alive0 = dones[r0] ? 0.f : 1.f;
            alive1 = dones[r1] ? 0.f : 1.f;
            E0 = Ein + (size_t)r0 * N;
            E1 = Ein + (size_t)r1 * N;
        }
#pragma unroll
        for (int ns = 0; ns < 4; ns++) {
            const int c = bcol + wn + ns * 8 + tig * 2;
            float b0 = 0.f, b1 = 0.f;
            if (hasb) { b0 = bias[c]; b1 = bias[c + 1]; }
            float v0 = acc[ms][ns][0] + b0;
            float v1 = acc[ms][ns][1] + b1;
            float v2 = acc[ms][ns][2] + b0;
            float v3 = acc[ms][ns][3] + b1;
            if (dorelu) {
                v0 = fmaxf(v0, 0.f); v1 = fmaxf(v1, 0.f);
                v2 = fmaxf(v2, 0.f); v3 = fmaxf(v3, 0.f);
            }
            if (resid) {
                v0 = (E0[c] + v0) * alive0;     v1 = (E0[c + 1] + v1) * alive0;
                v2 = (E1[c] + v2) * alive1;     v3 = (E1[c + 1] + v3) * alive1;
            }
            *(float2*)&Cout[(size_t)r0 * N + c] = make_float2(v0, v1);
            *(float2*)&Cout[(size_t)r1 * N + c] = make_float2(v2, v3);
        }
    }
}

// ---------------- persistent GRU scan ------------------------------------------
#define RPB 4
#define GTH 384
#define WHS_STRIDE 132
#define GRU_SMEM ((384 * WHS_STRIDE + RPB * D + RPB * 384 + D) * 4)

__global__ __launch_bounds__(GTH) void gru_kernel(
    const float* __restrict__ gi,
    const unsigned char* __restrict__ dones,
    const float* __restrict__ h0,
    const float* __restrict__ Wh,
    const float* __restrict__ bhn,
    float* __restrict__ e_out,
    float* __restrict__ hidden_out)
{
    extern __shared__ float sm[];
    float* Whs  = sm;
    float* hs   = Whs + 384 * WHS_STRIDE;
    float* ghs  = hs + RPB * D;
    float* sbhn = ghs + RPB * 384;

    const int tid = threadIdx.x;
    const int rowbase = blockIdx.x * RPB;

    for (int k = 0; k < D; k++)
        Whs[tid * WHS_STRIDE + k] = Wh[(size_t)k * (3 * D) + tid];
    if (tid < D) sbhn[tid] = bhn[tid];
    for (int idx = tid; idx < RPB * D; idx += GTH)
        hs[idx] = h0[(size_t)(rowbase + (idx >> 7)) * D + (idx & 127)];
    __syncthreads();

    for (int t = 0; t < T_STEPS; t++) {
        for (int idx = tid; idx < RPB * D; idx += GTH) {
            const int r = idx >> 7;
            if (dones[t * BATCH + rowbase + r]) hs[idx] = 0.f;
        }
        __syncthreads();

        {
            float a0 = 0.f, a1 = 0.f, a2 = 0.f, a3 = 0.f;
            const float* wp = Whs + tid * WHS_STRIDE;
#pragma unroll 8
            for (int k = 0; k < D; k += 4) {
                const float4 w4 = *(const float4*)(wp + k);
                float4 hv;
                hv = *(const float4*)(hs + 0 * D + k);
                a0 += w4.x * hv.x + w4.y * hv.y + w4.z * hv.z + w4.w * hv.w;
                hv = *(const float4*)(hs + 1 * D + k);
                a1 += w4.x * hv.x + w4.y * hv.y + w4.z * hv.z + w4.w * hv.w;
                hv = *(const float4*)(hs + 2 * D + k);
                a2 += w4.x * hv.x + w4.y * hv.y + w4.z * hv.z + w4.w * hv.w;
                hv = *(const float4*)(hs + 3 * D + k);
                a3 += w4.x * hv.x + w4.y * hv.y + w4.z * hv.z + w4.w * hv.w;
            }
            ghs[0 * 384 + tid] = a0;
            ghs[1 * 384 + tid] = a1;
            ghs[2 * 384 + tid] = a2;
            ghs[3 * 384 + tid] = a3;
        }
        __syncthreads();

        for (int idx = tid; idx < RPB * D; idx += GTH) {
            const int r = idx >> 7, d = idx & 127;
            const int row = rowbase + r;
            const size_t gib = ((size_t)t * BATCH + row) * (3 * D);
            const float i_r = gi[gib + d];
            const float i_z = gi[gib + D + d];
            const float i_n = gi[gib + 2 * D + d];
            const float h_r = ghs[r * 384 + d];
            const float h_z = ghs[r * 384 + D + d];
            const float h_n = ghs[r * 384 + 2 * D + d];
            const float hprev = hs[idx];
            const float rg = 1.f / (1.f + expf(-(i_r + h_r)));
            const float zg = 1.f / (1.f + expf(-(i_z + h_z)));
            const float ng = tanhf(i_n + rg * (h_n + sbhn[d]));
            const float hn = (1.f - zg) * ng + zg * hprev;
            hs[idx] = hn;
            const float alive = dones[t * BATCH + row] ? 0.f : 1.f;
            e_out[((size_t)t * BATCH + row) * D + d] = hn * alive;
        }
    }
    __syncthreads();
    for (int idx = tid; idx < RPB * D; idx += GTH)
        hidden_out[(size_t)(rowbase + (idx >> 7)) * D + (idx & 127)] = hs[idx];
}

// ---------------- fused pairwise-coupling C + context ---------------------------
// reads merged aiaj (row stride 256: [ai | aj])
__global__ __launch_bounds__(256) void couple_ctx_kernel(
    const float* __restrict__ e, const float* __restrict__ aiaj,
    const float* __restrict__ chb,
    const float* __restrict__ cow, const float* __restrict__ cob,
    const unsigned char* __restrict__ dones, float* __restrict__ ctx)
{
    __shared__ float sai[NA * CH], saj[NA * CH], se[NA * D];
    __shared__ float sb[CH], sw[CH];
    __shared__ float sC[NA * NA];
    __shared__ float salive[NA];

    const int g  = blockIdx.x;        // t*NE + group
    const int t  = g >> 6;
    const int eg = g & 63;
    const size_t base  = (size_t)g * NA * D;
    const size_t base2 = (size_t)g * NA * 256;
    const int tid = threadIdx.x;

#pragma unroll
    for (int q = 0; q < 2; q++) {
        const int idx = (tid + q * 256) * 4;
        const int row = idx >> 8;
        const int col = idx & 255;
        const float4 v = *(const float4*)&aiaj[base2 + idx];
        if (col < 128) *(float4*)&sai[row * 128 + col] = v;
        else           *(float4*)&saj[row * 128 + col - 128] = v;
    }
    *(float4*)&se[tid * 4] = *(const float4*)&e[base + tid * 4];
    if (tid < CH) { sb[tid] = chb[tid]; sw[tid] = cow[tid]; }
    if (tid < NA) salive[tid] = dones[t * BATCH + eg * NA + tid] ? 0.f : 1.f;
    __syncthreads();

    const int warp = tid >> 5, lane = tid & 31;
    {
        const int i = warp;
        const float cb = cob[0];
        for (int j = 0; j < NA; j++) {
            float s = 0.f;
#pragma unroll
            for (int k = lane; k < CH; k += 32) {
                const float v = sai[i * CH + k] + saj[j * CH + k] + sb[k];
                s += fmaxf(v, 0.f) * sw[k];
            }
#pragma unroll
            for (int off = 16; off; off >>= 1) s += __shfl_xor_sync(0xffffffffu, s, off);
            if (lane == 0) {
                const float cv = 1.f / (1.f + expf(-(s + cb)));
                sC[i * NA + j] = (i == j) ? 0.f : cv * salive[j];
            }
        }
    }
    __syncthreads();

    for (int idx = tid; idx < NA * D; idx += 256) {
        const int i = idx >> 7, d = idx & 127;
        float s = 0.f;
#pragma unroll
        for (int j = 0; j < NA; j++) s += sC[i * NA + j] * se[j * D + d];
        ctx[base + idx] = s;
    }
}

// ---------------- final value projection (VH -> 1) ------------------------------
__global__ __launch_bounds__(256) void vout_kernel(
    const float* __restrict__ v2, const float* __restrict__ w,
    const float* __restrict__ b, float* __restrict__ out)
{
    __shared__ float sw[VH];
    const int tid = threadIdx.x;
    sw[tid] = w[tid];
    __syncthreads();
    const int warp = tid >> 5, lane = tid & 31;
    const int row = blockIdx.x * 8 + warp;
    const float* vp = v2 + (size_t)row * VH;
    float s = 0.f;
#pragma unroll
    for (int k = lane; k < VH; k += 32) s += vp[k] * sw[k];
#pragma unroll
    for (int off = 16; off; off >>= 1) s += __shfl_xor_sync(0xffffffffu, s, off);
    if (lane == 0) out[row] = s + b[0];
}

// ---------------- launcher -------------------------------------------------------
extern "C" void kernel_launch(void* const* d_in, const int* in_sizes, int n_in,
                              void* d_out, int out_size)
{
    const float* hidden = (const float*)d_in[0];
    const float* obs    = (const float*)d_in[1];
    const void*  dones_raw = d_in[2];
    const float* e1w = (const float*)d_in[3];
    const float* e1b = (const float*)d_in[4];
    const float* e2w = (const float*)d_in[5];
    const float* e2b = (const float*)d_in[6];
    const float* gWi = (const float*)d_in[7];
    const float* gbi = (const float*)d_in[8];
    const float* gWh = (const float*)d_in[9];
    const float* gbhn = (const float*)d_in[10];
    const float* chw = (const float*)d_in[11];
    const float* chb = (const float*)d_in[12];
    const float* cow = (const float*)d_in[13];
    const float* cob = (const float*)d_in[14];
    const float* uhw = (const float*)d_in[15];
    const float* uhb = (const float*)d_in[16];
    const float* uow = (const float*)d_in[17];
    const float* uob = (const float*)d_in[18];
    const float* v1w = (const float*)d_in[19];
    const float* v1b = (const float*)d_in[20];
    const float* v2w = (const float*)d_in[21];
    const float* v2b = (const float*)d_in[22];
    const float* vow = (const float*)d_in[23];
    const float* vob = (const float*)d_in[24];

    float* out_hidden = (float*)d_out;                 // (B, D)
    float* out_values = (float*)d_out + BATCH * D;     // (T, B)

    float *emb1, *emb2, *gi, *e, *aiaj, *ctx, *d1, *v1, *v2;
    unsigned char* dmask;
    cudaGetSymbolAddress((void**)&emb1, g_emb1);
    cudaGetSymbolAddress((void**)&emb2, g_emb2);
    cudaGetSymbolAddress((void**)&gi,   g_gi);
    cudaGetSymbolAddress((void**)&e,    g_e);
    cudaGetSymbolAddress((void**)&aiaj, g_aiaj);
    cudaGetSymbolAddress((void**)&ctx,  g_ctx);
    cudaGetSymbolAddress((void**)&d1,   g_d1);
    cudaGetSymbolAddress((void**)&v1,   g_v1);
    cudaGetSymbolAddress((void**)&v2,   g_v2);
    cudaGetSymbolAddress((void**)&dmask, g_dmask);

    cudaFuncSetAttribute(gru_kernel, cudaFuncAttributeMaxDynamicSharedMemorySize, GRU_SMEM);

    const int M = TB;
    const dim3 blk(256);

    detect_dones_kernel<<<1, 256>>>((const unsigned char*)dones_raw, TB);
    conv_dones_kernel<<<TB / 256, 256>>>(dones_raw, TB);

    // embed1: relu(obs @ e1w + e1b)
    tgemm_kernel<<<dim3(D / BN, M / BM), blk>>>(M, D, OBS, D, obs, e1w,
        nullptr, nullptr, e1b, emb1, 1, nullptr, nullptr);
    // embed2: relu(emb1 @ e2w + e2b)
    tgemm_kernel<<<dim3(D / BN, M / BM), blk>>>(M, D, D, D, emb1, e2w,
        nullptr, nullptr, e2b, emb2, 1, nullptr, nullptr);
    // gi = emb2 @ gWi + gbi
    tgemm_kernel<<<dim3(3 * D / BN, M / BM), blk>>>(M, 3 * D, D, 3 * D, emb2, gWi,
        nullptr, nullptr, gbi, gi, 0, nullptr, nullptr);
    // sequential GRU scan
    gru_kernel<<<BATCH / RPB, GTH, GRU_SMEM>>>(gi, dmask, hidden, gWh, gbhn, e, out_hidden);

    for (int it = 0; it < ITERS; it++) {
        // [ai | aj] = e @ [W1 | W2]  (one N=256 GEMM, column-split B)
        tgemm_kernel<<<dim3(2 * CH / BN, M / BM), blk>>>(M, 2 * CH, D, CH, e, chw,
            nullptr, chw + (size_t)D * CH, nullptr, aiaj, 8, nullptr, nullptr);
        couple_ctx_kernel<<<T_STEPS * NE, 256>>>(e, aiaj, chb, cow, cob, dmask, ctx);
        // d1 = relu(e @ U1 + ctx @ U2 + uhb)
        tgemm_kernel<<<dim3(D / BN, M / BM), blk>>>(M, D, D, D, e, uhw,
            ctx, uhw + (size_t)D * D, uhb, d1, 1 | 2, nullptr, nullptr);
        // e = (e + relu(d1 @ uow + uob)) * alive   (in place)
        tgemm_kernel<<<dim3(D / BN, M / BM), blk>>>(M, D, D, D, d1, uow,
            nullptr, nullptr, uob, e, 4, e, dmask);
    }

    // value head
    tgemm_kernel<<<dim3(VH / BN, M / BM), blk>>>(M, VH, D, VH, e, v1w,
        nullptr, nullptr, v1b, v1, 1, nullptr, nullptr);
    tgemm_kernel<<<dim3(VH / BN, M / BM), blk>>>(M, VH, VH, VH, v1, v2w,
        nullptr, nullptr, v2b, v2, 1, nullptr, nullptr);
    vout_kernel<<<TB / 8, 256>>>(v2, vow, vob, out_values);
}